// round 11
// baseline (speedup 1.0000x reference)
#include <cuda_runtime.h>
#include <cstdint>

#define N_NODES 16384
#define N_FEAT  16384
#define EMBED   64
#define BATCH   4096
#define N_EDGES 524288

#define MT     128
#define KT     32                     // sub-tile K
#define NITRM  (N_FEAT / (2 * KT))    // 256 macro iterations
#define ABYTES (MT * KT * 4)          // 16384
#define BBYTES (EMBED * KT * 4)       // 8192
#define STG    (ABYTES + BBYTES)      // 24576 per sub-tile
#define MSTG   (2 * STG)              // 49152 per macro stage
#define NSTAGE 3
#define GEMM_SMEM (NSTAGE * MSTG)     // 147456

// ---------------- device scratch ----------------
__device__ int   g_is64;
__device__ int   g_degcnt[N_NODES];
__device__ int   g_need[N_NODES];
__device__ float g_dinv[N_NODES];
__device__ int   g_nsel;
__device__ int   g_sel_src[N_EDGES];
__device__ int   g_sel_dst[N_EDGES];
__device__ float g_sel_nrm[N_EDGES];
__device__ __align__(16) float g_wt[EMBED * N_FEAT];   // W^T, RNA-rounded to tf32
__device__ __align__(16) float g_xw[N_NODES * EMBED];
__device__ __align__(16) float g_agg[N_NODES * EMBED];

// ---------------- helpers ----------------
__device__ __forceinline__ uint32_t f2tf32(float f) {
    uint32_t r;
    asm("cvt.rna.tf32.f32 %0, %1;" : "=r"(r) : "f"(f));
    return r;
}
__device__ __forceinline__ int load_idx(const void* p, long long i, int is64) {
    if (is64) return (int)(((const long long*)p)[i]);
    return ((const int*)p)[i];
}
__device__ __forceinline__ void cp16(uint32_t dst, const void* src) {
    asm volatile("cp.async.cg.shared.global [%0], [%1], 16;" :: "r"(dst), "l"(src) : "memory");
}
__device__ __forceinline__ void cp_commit() {
    asm volatile("cp.async.commit_group;" ::: "memory");
}
__device__ __forceinline__ void cp_wait1() {
    asm volatile("cp.async.wait_group 1;" ::: "memory");
}
__device__ __forceinline__ uint32_t lds32(uint32_t a) {
    uint32_t v;
    asm volatile("ld.shared.b32 %0, [%1];" : "=r"(v) : "r"(a));
    return v;
}

#define MMA(d, a0, a1, a2, a3, b0, b1)                                          \
    asm volatile(                                                                \
        "mma.sync.aligned.m16n8k8.row.col.f32.tf32.tf32.f32 "                    \
        "{%0,%1,%2,%3}, {%4,%5,%6,%7}, {%8,%9}, {%0,%1,%2,%3};"                  \
        : "+f"((d)[0]), "+f"((d)[1]), "+f"((d)[2]), "+f"((d)[3])                 \
        : "r"(a0), "r"(a1), "r"(a2), "r"(a3), "r"(b0), "r"(b1))

// ---------------- small kernels ----------------
__global__ void k_detect(const void* __restrict__ x) {
    const long long* p = (const long long*)x;
    int lane = threadIdx.x;
    long long v0 = p[lane];
    long long v1 = p[lane + 32];
    int ok = (v0 >= 0 && v0 < N_NODES && v1 >= 0 && v1 < N_NODES);
    unsigned m = __ballot_sync(0xFFFFFFFFu, ok);
    if (lane == 0) g_is64 = (m == 0xFFFFFFFFu);
}
__global__ void k_zero() {
    int i = blockIdx.x * blockDim.x + threadIdx.x;
    g_degcnt[i] = 0;
    g_need[i] = 0;
    if (i == 0) g_nsel = 0;
}
__global__ void k_deg_mark(const void* __restrict__ edges, const void* __restrict__ x) {
    int t = blockIdx.x * blockDim.x + threadIdx.x;
    int is64 = g_is64;
    if (t < N_EDGES) {
        int dst = load_idx(edges, (long long)N_EDGES + t, is64);
        atomicAdd(&g_degcnt[dst], 1);
    } else {
        int i = load_idx(x, t - N_EDGES, is64);
        g_need[i] = 1;
    }
}
__global__ void k_dinv() {
    int i = blockIdx.x * blockDim.x + threadIdx.x;
    g_dinv[i] = rsqrtf(1.0f + (float)g_degcnt[i]);
}

// ---------------- W transpose (tiled, coalesced): g_wt[n][k] = tf32(W[k][n]) --
__global__ void __launch_bounds__(256) k_prep_wt(const float* __restrict__ W) {
    __shared__ float t[64][65];
    const int kb = blockIdx.x * 64;
    const int r = threadIdx.x >> 4;
    const int c = threadIdx.x & 15;
#pragma unroll
    for (int i = 0; i < 4; i++) {
        int row = r + 16 * i;
        float4 v = *(const float4*)(W + (long long)(kb + row) * EMBED + c * 4);
        t[row][c * 4 + 0] = v.x;
        t[row][c * 4 + 1] = v.y;
        t[row][c * 4 + 2] = v.z;
        t[row][c * 4 + 3] = v.w;
    }
    __syncthreads();
#pragma unroll
    for (int i = 0; i < 4; i++) {
        int n = r + 16 * i;
        float4 u;
        u.x = __uint_as_float(f2tf32(t[c * 4 + 0][n]));
        u.y = __uint_as_float(f2tf32(t[c * 4 + 1][n]));
        u.z = __uint_as_float(f2tf32(t[c * 4 + 2][n]));
        u.w = __uint_as_float(f2tf32(t[c * 4 + 3][n]));
        *(float4*)(g_wt + (long long)n * N_FEAT + kb + c * 4) = u;
    }
}

// ---------------- GEMM: g_xw = X @ W  (tf32 mma.sync) ----------------
// CTA 128x64, 256 thr (8 warps), 1 CTA/SM. Warp: mhalf=wid&1 (64 rows),
// khalf=wid>>1 (k8 slice of each KT=32 sub-tile). 3 macro stages of KT=64
// (2 sub-tiles), one wait+barrier per macro iter (256 total).
struct Frag {
    uint32_t a[4][4];
    uint32_t b[8][2];
};

__global__ void __launch_bounds__(256, 1) k_gemm_mma(const float* __restrict__ X) {
    extern __shared__ __align__(16) char smem[];
    const uint32_t sb = (uint32_t)__cvta_generic_to_shared(smem);

    const int tid  = threadIdx.x;
    const int wid  = tid >> 5;
    const int lane = tid & 31;
    const int mhalf = wid & 1;
    const int khalf = wid >> 1;          // 0..3
    const int tf = lane >> 2;            // 0..7
    const int tk = lane & 3;             // 0..3
    const long long rb = (long long)blockIdx.x * MT;

    // ---- producer addressing (per sub-tile: 4 A chunks + 2 B chunks/thread)
    const int q  = tid & 7;
    const int r0 = tid >> 3;
    const uint32_t dsw = (uint32_t)((q ^ (r0 & 7)) << 4);
    uint32_t adst[4], bdst[2];
    const float* asrc[4];
    const float* bsrc[2];
#pragma unroll
    for (int i = 0; i < 4; i++) {
        adst[i] = (uint32_t)((r0 + 32 * i) * 128) + dsw;
        asrc[i] = X + (rb + r0 + 32 * i) * (long long)N_FEAT + q * 4;
    }
#pragma unroll
    for (int i = 0; i < 2; i++) {
        bdst[i] = (uint32_t)(ABYTES + (r0 + 32 * i) * 128) + dsw;
        bsrc[i] = g_wt + (long long)(r0 + 32 * i) * N_FEAT + q * 4;
    }

    // ---- consumer offsets (within one sub-tile)
    const uint32_t csw = (uint32_t)(((2 * khalf) ^ tf) << 4) + (uint32_t)(tk * 4);
    uint32_t ao[4], bo[8];
#pragma unroll
    for (int mf = 0; mf < 4; mf++)
        ao[mf] = (uint32_t)((mhalf * 64 + mf * 16 + tf) * 128) + csw;
#pragma unroll
    for (int nf = 0; nf < 8; nf++)
        bo[nf] = (uint32_t)(ABYTES + (nf * 8 + tf) * 128) + csw;

    float acc[4][8][4] = {};
    Frag f0, f1;

#define REFILL(t)                                                               \
    do {                                                                        \
        if ((t) < NITRM) {                                                      \
            const uint32_t st_ = sb + ((t) % NSTAGE) * MSTG;                    \
            const int ko_ = (t) * 2 * KT;                                       \
            _Pragma("unroll")                                                   \
            for (int sub_ = 0; sub_ < 2; sub_++) {                              \
                _Pragma("unroll")                                               \
                for (int i_ = 0; i_ < 4; i_++)                                  \
                    cp16(st_ + sub_ * STG + adst[i_],                           \
                         asrc[i_] + ko_ + sub_ * KT);                           \
                _Pragma("unroll")                                               \
                for (int i_ = 0; i_ < 2; i_++)                                  \
                    cp16(st_ + sub_ * STG + bdst[i_],                           \
                         bsrc[i_] + ko_ + sub_ * KT);                           \
            }                                                                   \
        }                                                                       \
        cp_commit();                                                            \
    } while (0)

#define PREFETCH(t, sub, F)                                                     \
    do {                                                                        \
        const uint32_t st_ = sb + ((t) % NSTAGE) * MSTG + (sub) * STG;          \
        _Pragma("unroll")                                                       \
        for (int nf_ = 0; nf_ < 8; nf_++) {                                     \
            (F).b[nf_][0] = lds32(st_ + bo[nf_]);                               \
            (F).b[nf_][1] = lds32(st_ + (bo[nf_] ^ 16));                        \
        }                                                                       \
        _Pragma("unroll")                                                       \
        for (int mf_ = 0; mf_ < 4; mf_++) {                                     \
            (F).a[mf_][0] = f2tf32(__uint_as_float(lds32(st_ + ao[mf_])));      \
            (F).a[mf_][1] = f2tf32(__uint_as_float(lds32(st_ + ao[mf_] + 1024)));\
            (F).a[mf_][2] = f2tf32(__uint_as_float(lds32(st_ + (ao[mf_] ^ 16))));\
            (F).a[mf_][3] = f2tf32(__uint_as_float(lds32(st_ + (ao[mf_] ^ 16) + 1024)));\
        }                                                                       \
    } while (0)

#define MMALL(F)                                                                \
    do {                                                                        \
        _Pragma("unroll")                                                       \
        for (int mf_ = 0; mf_ < 4; mf_++)                                       \
            _Pragma("unroll")                                                   \
            for (int nf_ = 0; nf_ < 8; nf_++)                                   \
                MMA(acc[mf_][nf_], (F).a[mf_][0], (F).a[mf_][1],                \
                    (F).a[mf_][2], (F).a[mf_][3],                               \
                    (F).b[nf_][0], (F).b[nf_][1]);                              \
    } while (0)

    // ---- prologue: commit macro stages 0,1
#pragma unroll
    for (int s = 0; s < 2; s++) REFILL(s);
    cp_wait1();                 // stage 0 landed (this thread)
    __syncthreads();            // ... for ALL threads
    PREFETCH(0, 0, f0);

    // invariant at top of iter kt: stage kt landed & visible to all;
    // f0 = frags(kt, sub0); slot (kt+2)%3 (stage kt-1) fully consumed
    // (its last LDS was PREFETCH(kt-1,1) before the prior barrier).
    for (int kt = 0; kt < NITRM; kt++) {
        REFILL(kt + 2);
        PREFETCH(kt, 1, f1);
        MMALL(f0);
        MMALL(f1);
        cp_wait1();             // stage kt+1 landed (only refill kt+2 pending)
        __syncthreads();        // landed for all; stage kt reads done everywhere
        if (kt + 1 < NITRM) PREFETCH(kt + 1, 0, f0);
    }
    __syncthreads();

    // ---- epilogue: merge 4 khalf partials via smem (6 x 16KB regions)
    if (khalf != 0) {
        const int p = (khalf - 1) * 2 + mhalf;
        float4* stp = (float4*)(smem + p * 16384);
#pragma unroll
        for (int mf = 0; mf < 4; mf++)
#pragma unroll
            for (int nf = 0; nf < 8; nf++)
                stp[(mf * 8 + nf) * 32 + lane] =
                    make_float4(acc[mf][nf][0], acc[mf][nf][1],
                                acc[mf][nf][2], acc[mf][nf][3]);
    }
    __syncthreads();
    if (khalf == 0) {
        const float4* p0 = (const float4*)(smem + (0 + mhalf) * 16384);
        const float4* p1 = (const float4*)(smem + (2 + mhalf) * 16384);
        const float4* p2 = (const float4*)(smem + (4 + mhalf) * 16384);
#pragma unroll
        for (int mf = 0; mf < 4; mf++) {
#pragma unroll
            for (int nf = 0; nf < 8; nf++) {
                const int o = (mf * 8 + nf) * 32 + lane;
                float4 u = p0[o], v = p1[o], w = p2[o];
                float c0 = acc[mf][nf][0] + u.x + v.x + w.x;
                float c1 = acc[mf][nf][1] + u.y + v.y + w.y;
                float c2 = acc[mf][nf][2] + u.z + v.z + w.z;
                float c3 = acc[mf][nf][3] + u.w + v.w + w.w;
                long long row = rb + mhalf * 64 + mf * 16 + tf;
                int col = nf * 8 + 2 * tk;
                *(float2*)(g_xw + row * EMBED + col)       = make_float2(c0, c1);
                *(float2*)(g_xw + (row + 8) * EMBED + col) = make_float2(c2, c3);
            }
        }
    }
}

// ---------------- edge compaction: keep edges whose dst is referenced --------
__global__ void k_edge_sel(const void* __restrict__ edges) {
    int e = blockIdx.x * blockDim.x + threadIdx.x;
    int is64 = g_is64;
    int dst = load_idx(edges, (long long)N_EDGES + e, is64);
    if (!g_need[dst]) return;
    int src = load_idx(edges, e, is64);
    int pos = atomicAdd(&g_nsel, 1);
    g_sel_src[pos] = src;
    g_sel_dst[pos] = dst;
    g_sel_nrm[pos] = g_dinv[src] * g_dinv[dst];
}

// ---------------- aggregation init: self-loop term + bias ----------------
__global__ void k_agg_init(const float* __restrict__ b_gcn) {
    int i = blockIdx.x * blockDim.x + threadIdx.x;
    int n = i >> 6;
    int d = i & 63;
    float di = g_dinv[n];
    g_agg[i] = g_xw[i] * di * di + b_gcn[d];
}

// ---------------- edge aggregation (grid-stride over compacted list) ---------
__global__ void k_agg_edges() {
    const long long total = (long long)g_nsel * 16;
    const long long stride = (long long)gridDim.x * blockDim.x;
    for (long long t = (long long)blockIdx.x * blockDim.x + threadIdx.x;
         t < total; t += stride) {
        int e = (int)(t >> 4);
        int qd = (int)(t & 15);
        int src = g_sel_src[e];
        int dst = g_sel_dst[e];
        float nrm = g_sel_nrm[e];
        float4 v = ((const float4*)(g_xw + (long long)src * EMBED))[qd];
        float* o = g_agg + (long long)dst * EMBED + qd * 4;
        atomicAdd(o + 0, v.x * nrm);
        atomicAdd(o + 1, v.y * nrm);
        atomicAdd(o + 2, v.z * nrm);
        atomicAdd(o + 3, v.w * nrm);
    }
}

// ---------------- final head: lin + dot(emb0, emb1) ----------------
__global__ void k_final(const void* __restrict__ x,
                        const float* __restrict__ w_lin,
                        const float* __restrict__ b_lin,
                        float* __restrict__ out) {
    int b = blockIdx.x * (blockDim.x >> 5) + (threadIdx.x >> 5);
    int lane = threadIdx.x & 31;
    if (b >= BATCH) return;
    int is64 = g_is64;
    int i0 = load_idx(x, 2LL * b, is64);
    int i1 = load_idx(x, 2LL * b + 1, is64);
    const float* e0 = &g_agg[(long long)i0 * EMBED];
    const float* e1 = &g_agg[(long long)i1 * EMBED];
    float s = e0[lane] * e1[lane] + e0[lane + 32] * e1[lane + 32];
#pragma unroll
    for (int o = 16; o; o >>= 1) s += __shfl_xor_sync(0xFFFFFFFFu, s, o);
    if (lane == 0) out[b] = s + w_lin[i0] + w_lin[i1] + b_lin[0];
}

// ---------------- launch (GEMM kept 4th: the ncu-profiled slot) ---------------
extern "C" void kernel_launch(void* const* d_in, const int* in_sizes, int n_in,
                              void* d_out, int out_size) {
    const void*  x     = d_in[0];
    const float* X     = (const float*)d_in[1];
    const void*  edges = d_in[2];
    const float* Wg    = (const float*)d_in[3];
    const float* bg    = (const float*)d_in[4];
    const float* wl    = (const float*)d_in[5];
    const float* bl    = (const float*)d_in[6];
    float* out = (float*)d_out;

    cudaFuncSetAttribute(k_gemm_mma, cudaFuncAttributeMaxDynamicSharedMemorySize, GEMM_SMEM);

    k_detect<<<1, 32>>>(x);                                       // 1
    k_prep_wt<<<N_FEAT / 64, 256>>>(Wg);                          // 2
    k_zero<<<N_NODES / 256, 256>>>();                             // 3
    k_gemm_mma<<<N_NODES / MT, 256, GEMM_SMEM>>>(X);              // 4 <- profiled
    k_deg_mark<<<(N_EDGES + 2 * BATCH) / 256, 256>>>(edges, x);   // 5
    k_dinv<<<N_NODES / 256, 256>>>();                             // 6
    k_edge_sel<<<N_EDGES / 256, 256>>>(edges);                    // 7
    k_agg_init<<<(N_NODES * EMBED) / 256, 256>>>(bg);             // 8
    k_agg_edges<<<2048, 256>>>();                                 // 9
    k_final<<<BATCH / 8, 256>>>(x, wl, bl, out);                  // 10
}

// round 12
// speedup vs baseline: 1.6938x; 1.6938x over previous
#include <cuda_runtime.h>
#include <cstdint>

#define N_NODES 16384
#define N_FEAT  16384
#define EMBED   64
#define BATCH   4096
#define N_EDGES 524288

#define MT     128
#define KT     32
#define NITR   (N_FEAT / KT)          // 512
#define ABYTES (MT * KT * 4)          // 16384
#define BBYTES (EMBED * KT * 4)       // 8192
#define STG    (ABYTES + BBYTES)      // 24576
#define NSTAGE 8
#define GEMM_SMEM (NSTAGE * STG)      // 196608

// ---------------- device scratch ----------------
__device__ int   g_is64;
__device__ int   g_degcnt[N_NODES];
__device__ int   g_need[N_NODES];
__device__ float g_dinv[N_NODES];
__device__ int   g_nsel;
__device__ int   g_sel_src[N_EDGES];
__device__ int   g_sel_dst[N_EDGES];
__device__ float g_sel_nrm[N_EDGES];
__device__ __align__(16) float g_wt[EMBED * N_FEAT];   // W^T, RNA-rounded to tf32
__device__ __align__(16) float g_xw[N_NODES * EMBED];
__device__ __align__(16) float g_agg[N_NODES * EMBED];

// ---------------- helpers ----------------
__device__ __forceinline__ uint32_t f2tf32(float f) {
    uint32_t r;
    asm("cvt.rna.tf32.f32 %0, %1;" : "=r"(r) : "f"(f));
    return r;
}
__device__ __forceinline__ int load_idx(const void* p, long long i, int is64) {
    if (is64) return (int)(((const long long*)p)[i]);
    return ((const int*)p)[i];
}
__device__ __forceinline__ void cp16(uint32_t dst, const void* src) {
    asm volatile("cp.async.cg.shared.global [%0], [%1], 16;" :: "r"(dst), "l"(src) : "memory");
}
__device__ __forceinline__ void cp_commit() {
    asm volatile("cp.async.commit_group;" ::: "memory");
}
__device__ __forceinline__ void cp_wait5() {
    asm volatile("cp.async.wait_group 5;" ::: "memory");
}

#define LDSM4(r0, r1, r2, r3, addr)                                             \
    asm volatile("ldmatrix.sync.aligned.m8n8.x4.shared.b16 {%0,%1,%2,%3}, [%4];"\
                 : "=r"(r0), "=r"(r1), "=r"(r2), "=r"(r3) : "r"(addr))

#define MMA(d, a0, a1, a2, a3, b0, b1)                                          \
    asm volatile(                                                                \
        "mma.sync.aligned.m16n8k8.row.col.f32.tf32.tf32.f32 "                    \
        "{%0,%1,%2,%3}, {%4,%5,%6,%7}, {%8,%9}, {%0,%1,%2,%3};"                  \
        : "+f"((d)[0]), "+f"((d)[1]), "+f"((d)[2]), "+f"((d)[3])                 \
        : "r"(a0), "r"(a1), "r"(a2), "r"(a3), "r"(b0), "r"(b1))

// ---------------- small kernels ----------------
__global__ void k_detect(const void* __restrict__ x) {
    const long long* p = (const long long*)x;
    int lane = threadIdx.x;
    long long v0 = p[lane];
    long long v1 = p[lane + 32];
    int ok = (v0 >= 0 && v0 < N_NODES && v1 >= 0 && v1 < N_NODES);
    unsigned m = __ballot_sync(0xFFFFFFFFu, ok);
    if (lane == 0) g_is64 = (m == 0xFFFFFFFFu);
}
__global__ void k_zero() {
    int i = blockIdx.x * blockDim.x + threadIdx.x;
    g_degcnt[i] = 0;
    g_need[i] = 0;
    if (i == 0) g_nsel = 0;
}
__global__ void k_deg_mark(const void* __restrict__ edges, const void* __restrict__ x) {
    int t = blockIdx.x * blockDim.x + threadIdx.x;
    int is64 = g_is64;
    if (t < N_EDGES) {
        int dst = load_idx(edges, (long long)N_EDGES + t, is64);
        atomicAdd(&g_degcnt[dst], 1);
    } else {
        int i = load_idx(x, t - N_EDGES, is64);
        g_need[i] = 1;
    }
}
__global__ void k_dinv() {
    int i = blockIdx.x * blockDim.x + threadIdx.x;
    g_dinv[i] = rsqrtf(1.0f + (float)g_degcnt[i]);
}

// ---------------- W transpose (tiled, coalesced): g_wt[n][k] = tf32(W[k][n]) --
__global__ void __launch_bounds__(256) k_prep_wt(const float* __restrict__ W) {
    __shared__ float t[64][65];
    const int kb = blockIdx.x * 64;
    const int r = threadIdx.x >> 4;
    const int c = threadIdx.x & 15;
#pragma unroll
    for (int i = 0; i < 4; i++) {
        int row = r + 16 * i;
        float4 v = *(const float4*)(W + (long long)(kb + row) * EMBED + c * 4);
        t[row][c * 4 + 0] = v.x;
        t[row][c * 4 + 1] = v.y;
        t[row][c * 4 + 2] = v.z;
        t[row][c * 4 + 3] = v.w;
    }
    __syncthreads();
#pragma unroll
    for (int i = 0; i < 4; i++) {
        int n = r + 16 * i;
        float4 u;
        u.x = __uint_as_float(f2tf32(t[c * 4 + 0][n]));
        u.y = __uint_as_float(f2tf32(t[c * 4 + 1][n]));
        u.z = __uint_as_float(f2tf32(t[c * 4 + 2][n]));
        u.w = __uint_as_float(f2tf32(t[c * 4 + 3][n]));
        *(float4*)(g_wt + (long long)n * N_FEAT + kb + c * 4) = u;
    }
}

// ---------------- GEMM: g_xw = X @ W  (tf32 mma.sync + ldmatrix) -------------
// CTA 128x64, 256 thr (8 warps), 1 CTA/SM. Warp: mhalf=wid&1 (64 rows),
// khalf=wid>>1 (k8 slice of KT=32). 8-stage cp.async pipeline (wait_group 5),
// ONE barrier/iter, register fragment double-buffering, LDSM.x4 fragment loads.
struct Frag {
    uint32_t a[4][4];
    uint32_t b[8][2];
};

__global__ void __launch_bounds__(256, 1) k_gemm_mma(const float* __restrict__ X) {
    extern __shared__ __align__(16) char smem[];
    const uint32_t sb = (uint32_t)__cvta_generic_to_shared(smem);

    const int tid  = threadIdx.x;
    const int wid  = tid >> 5;
    const int lane = tid & 31;
    const int mhalf = wid & 1;
    const int khalf = wid >> 1;          // 0..3
    const int tf = lane >> 2;            // 0..7
    const int tk = lane & 3;             // 0..3
    const long long rb = (long long)blockIdx.x * MT;

    // ---- producer addressing: 4 A chunks + 2 B chunks per thread per stage
    const int q  = tid & 7;
    const int r0 = tid >> 3;
    const uint32_t dsw = (uint32_t)((q ^ (r0 & 7)) << 4);
    uint32_t adst[4], bdst[2];
    const float* asrc[4];
    const float* bsrc[2];
#pragma unroll
    for (int i = 0; i < 4; i++) {
        adst[i] = (uint32_t)((r0 + 32 * i) * 128) + dsw;
        asrc[i] = X + (rb + r0 + 32 * i) * (long long)N_FEAT + q * 4;
    }
#pragma unroll
    for (int i = 0; i < 2; i++) {
        bdst[i] = (uint32_t)(ABYTES + (r0 + 32 * i) * 128) + dsw;
        bsrc[i] = g_wt + (long long)(r0 + 32 * i) * N_FEAT + q * 4;
    }

    // ---- LDSM lane addressing (stage-relative offsets)
    // A x4 for mf: quad 0: rows +0..7 chunk c0 | quad 1: rows +8..15 chunk c0
    //              quad 2: rows +0..7 chunk c0+1 | quad 3: rows +8..15 chunk c0+1
    // -> regs (a0,a1,a2,a3) exactly matching the m16n8k8 tf32 A fragment.
    const int quad = lane >> 3;
    const int lrow = lane & 7;
    uint32_t aoff[4], boff[4];
#pragma unroll
    for (int mf = 0; mf < 4; mf++) {
        int arow = mhalf * 64 + mf * 16 + (quad & 1) * 8 + lrow;
        int ach  = 2 * khalf + (quad >> 1);
        aoff[mf] = (uint32_t)(arow * 128 + ((ach ^ (arow & 7)) << 4));
    }
    // B x4 p: p&1 = n-group (n 0-31 / 32-63), p>>1 = k-half (b0 / b1);
    // lane L -> row L of the 32-row group; regs = b of nf (4 per x4).
#pragma unroll
    for (int p = 0; p < 4; p++) {
        int brow = (p & 1) * 32 + lane;
        int bch  = 2 * khalf + (p >> 1);
        boff[p] = (uint32_t)(ABYTES + brow * 128 + ((bch ^ (brow & 7)) << 4));
    }

    float acc[4][8][4] = {};
    Frag f0, f1;

#define REFILL(t)                                                               \
    do {                                                                        \
        if ((t) < NITR) {                                                       \
            const uint32_t st_ = sb + ((t) % NSTAGE) * STG;                     \
            const int ko_ = (t) * KT;                                           \
            _Pragma("unroll")                                                   \
            for (int i_ = 0; i_ < 4; i_++) cp16(st_ + adst[i_], asrc[i_] + ko_);\
            _Pragma("unroll")                                                   \
            for (int i_ = 0; i_ < 2; i_++) cp16(st_ + bdst[i_], bsrc[i_] + ko_);\
        }                                                                       \
        cp_commit();                                                            \
    } while (0)

#define PREFETCH(t, F)                                                          \
    do {                                                                        \
        const uint32_t st_ = sb + ((t) % NSTAGE) * STG;                         \
        LDSM4((F).b[0][0], (F).b[1][0], (F).b[2][0], (F).b[3][0], st_ + boff[0]);\
        LDSM4((F).b[4][0], (F).b[5][0], (F).b[6][0], (F).b[7][0], st_ + boff[1]);\
        LDSM4((F).b[0][1], (F).b[1][1], (F).b[2][1], (F).b[3][1], st_ + boff[2]);\
        LDSM4((F).b[4][1], (F).b[5][1], (F).b[6][1], (F).b[7][1], st_ + boff[3]);\
        _Pragma("unroll")                                                       \
        for (int mf_ = 0; mf_ < 4; mf_++) {                                     \
            LDSM4((F).a[mf_][0], (F).a[mf_][1], (F).a[mf_][2], (F).a[mf_][3],   \
                  st_ + aoff[mf_]);                                             \
            _Pragma("unroll")                                                   \
            for (int j_ = 0; j_ < 4; j_++)                                      \
                (F).a[mf_][j_] = f2tf32(__uint_as_float((F).a[mf_][j_]));       \
        }                                                                       \
    } while (0)

#define MMALL(F)                                                                \
    do {                                                                        \
        _Pragma("unroll")                                                       \
        for (int mf_ = 0; mf_ < 4; mf_++)                                       \
            _Pragma("unroll")                                                   \
            for (int nf_ = 0; nf_ < 8; nf_++)                                   \
                MMA(acc[mf_][nf_], (F).a[mf_][0], (F).a[mf_][1],                \
                    (F).a[mf_][2], (F).a[mf_][3],                               \
                    (F).b[nf_][0], (F).b[nf_][1]);                              \
    } while (0)

    // ---- prologue: commit tiles 0..6 (7 groups)
#pragma unroll
    for (int s = 0; s < NSTAGE - 1; s++) {
        const uint32_t st = sb + s * STG;
        const int ko = s * KT;
#pragma unroll
        for (int i = 0; i < 4; i++) cp16(st + adst[i], asrc[i] + ko);
#pragma unroll
        for (int i = 0; i < 2; i++) cp16(st + bdst[i], bsrc[i] + ko);
        cp_commit();
    }
    cp_wait5();                 // tiles 0,1 landed (this thread)
    __syncthreads();            // ... for ALL threads
    PREFETCH(0, f0);

    // invariant at top of iter kt: tiles <= kt+1 landed & visible to all;
    // slot (kt+7)%8 (tile kt-1): its last LDSM was at iter kt-2, sealed by
    // two barriers since -> overwrite safe.
    for (int kt = 0; kt < NITR; kt += 2) {
        // even iter: consume f0 (tile kt), prefetch tile kt+1
        REFILL(kt + 7);
        PREFETCH(kt + 1, f1);
        MMALL(f0);
        cp_wait5();
        __syncthreads();
        // odd iter: consume f1 (tile kt+1), prefetch tile kt+2
        REFILL(kt + 8);
        if (kt + 2 < NITR) PREFETCH(kt + 2, f0);
        MMALL(f1);
        cp_wait5();
        __syncthreads();
    }

    // ---- epilogue: merge 4 khalf partials via smem (6 x 16KB regions)
    if (khalf != 0) {
        const int p = (khalf - 1) * 2 + mhalf;
        float4* stp = (float4*)(smem + p * 16384);
#pragma unroll
        for (int mf = 0; mf < 4; mf++)
#pragma unroll
            for (int nf = 0; nf < 8; nf++)
                stp[(mf * 8 + nf) * 32 + lane] =
                    make_float4(acc[mf][nf][0], acc[mf][nf][1],
                                acc[mf][nf][2], acc[mf][nf][3]);
    }
    __syncthreads();
    if (khalf == 0) {
        const float4* p0 = (const float4*)(smem + (0 + mhalf) * 16384);
        const float4* p1 = (const float4*)(smem + (2 + mhalf) * 16384);
        const float4* p2 = (const float4*)(smem + (4 + mhalf) * 16384);
#pragma unroll
        for (int mf = 0; mf < 4; mf++) {
#pragma unroll
            for (int nf = 0; nf < 8; nf++) {
                const int o = (mf * 8 + nf) * 32 + lane;
                float4 u = p0[o], v = p1[o], w = p2[o];
                float c0 = acc[mf][nf][0] + u.x + v.x + w.x;
                float c1 = acc[mf][nf][1] + u.y + v.y + w.y;
                float c2 = acc[mf][nf][2] + u.z + v.z + w.z;
                float c3 = acc[mf][nf][3] + u.w + v.w + w.w;
                long long row = rb + mhalf * 64 + mf * 16 + tf;
                int col = nf * 8 + 2 * tk;
                *(float2*)(g_xw + row * EMBED + col)       = make_float2(c0, c1);
                *(float2*)(g_xw + (row + 8) * EMBED + col) = make_float2(c2, c3);
            }
        }
    }
}

// ---------------- edge compaction: keep edges whose dst is referenced --------
__global__ void k_edge_sel(const void* __restrict__ edges) {
    int e = blockIdx.x * blockDim.x + threadIdx.x;
    int is64 = g_is64;
    int dst = load_idx(edges, (long long)N_EDGES + e, is64);
    if (!g_need[dst]) return;
    int src = load_idx(edges, e, is64);
    int pos = atomicAdd(&g_nsel, 1);
    g_sel_src[pos] = src;
    g_sel_dst[pos] = dst;
    g_sel_nrm[pos] = g_dinv[src] * g_dinv[dst];
}

// ---------------- aggregation init: self-loop term + bias ----------------
__global__ void k_agg_init(const float* __restrict__ b_gcn) {
    int i = blockIdx.x * blockDim.x + threadIdx.x;
    int n = i >> 6;
    int d = i & 63;
    float di = g_dinv[n];
    g_agg[i] = g_xw[i] * di * di + b_gcn[d];
}

// ---------------- edge aggregation (grid-stride over compacted list) ---------
__global__ void k_agg_edges() {
    const long long total = (long long)g_nsel * 16;
    const long long stride = (long long)gridDim.x * blockDim.x;
    for (long long t = (long long)blockIdx.x * blockDim.x + threadIdx.x;
         t < total; t += stride) {
        int e = (int)(t >> 4);
        int qd = (int)(t & 15);
        int src = g_sel_src[e];
        int dst = g_sel_dst[e];
        float nrm = g_sel_nrm[e];
        float4 v = ((const float4*)(g_xw + (long long)src * EMBED))[qd];
        float* o = g_agg + (long long)dst * EMBED + qd * 4;
        atomicAdd(o + 0, v.x * nrm);
        atomicAdd(o + 1, v.y * nrm);
        atomicAdd(o + 2, v.z * nrm);
        atomicAdd(o + 3, v.w * nrm);
    }
}

// ---------------- final head: lin + dot(emb0, emb1) ----------------
__global__ void k_final(const void* __restrict__ x,
                        const float* __restrict__ w_lin,
                        const float* __restrict__ b_lin,
                        float* __restrict__ out) {
    int b = blockIdx.x * (blockDim.x >> 5) + (threadIdx.x >> 5);
    int lane = threadIdx.x & 31;
    if (b >= BATCH) return;
    int is64 = g_is64;
    int i0 = load_idx(x, 2LL * b, is64);
    int i1 = load_idx(x, 2LL * b + 1, is64);
    const float* e0 = &g_agg[(long long)i0 * EMBED];
    const float* e1 = &g_agg[(long long)i1 * EMBED];
    float s = e0[lane] * e1[lane] + e0[lane + 32] * e1[lane + 32];
#pragma unroll
    for (int o = 16; o; o >>= 1) s += __shfl_xor_sync(0xFFFFFFFFu, s, o);
    if (lane == 0) out[b] = s + w_lin[i0] + w_lin[i1] + b_lin[0];
}

// ---------------- launch (GEMM kept 4th: the ncu-profiled slot) ---------------
extern "C" void kernel_launch(void* const* d_in, const int* in_sizes, int n_in,
                              void* d_out, int out_size) {
    const void*  x     = d_in[0];
    const float* X     = (const float*)d_in[1];
    const void*  edges = d_in[2];
    const float* Wg    = (const float*)d_in[3];
    const float* bg    = (const float*)d_in[4];
    const float* wl    = (const float*)d_in[5];
    const float* bl    = (const float*)d_in[6];
    float* out = (float*)d_out;

    cudaFuncSetAttribute(k_gemm_mma, cudaFuncAttributeMaxDynamicSharedMemorySize, GEMM_SMEM);

    k_detect<<<1, 32>>>(x);                                       // 1
    k_prep_wt<<<N_FEAT / 64, 256>>>(Wg);                          // 2
    k_zero<<<N_NODES / 256, 256>>>();                             // 3
    k_gemm_mma<<<N_NODES / MT, 256, GEMM_SMEM>>>(X);              // 4 <- profiled
    k_deg_mark<<<(N_EDGES + 2 * BATCH) / 256, 256>>>(edges, x);   // 5
    k_dinv<<<N_NODES / 256, 256>>>();                             // 6
    k_edge_sel<<<N_EDGES / 256, 256>>>(edges);                    // 7
    k_agg_init<<<(N_NODES * EMBED) / 256, 256>>>(bg);             // 8
    k_agg_edges<<<2048, 256>>>();                                 // 9
    k_final<<<BATCH / 8, 256>>>(x, wl, bl, out);                  // 10
}